// round 3
// baseline (speedup 1.0000x reference)
#include <cuda_runtime.h>
#include <cuda_bf16.h>
#include <cstdint>

#define NUM_CLASSES 1000
#define EMBED_DIM   1024
#define VEC4        (EMBED_DIM / 4)   // 256 float4 per row
#define FACTOR      0.3f
#define CAP         160               // max rows per class (E[n]=32.8, sigma=5.7)

// Scratch (__device__ globals: no allocation allowed).
// INVARIANT: g_count is all-zero at entry of every kernel_launch execution.
//  - zero-initialized at module load (first correctness run)
//  - K2 resets its class counter after reading it (every run, incl. replays)
// Graph capture itself executes nothing, so the invariant survives capture.
__device__ int g_count[NUM_CLASSES];
__device__ int g_perm[NUM_CLASSES * CAP];

// K1: bucket rows by class. int4-vectorized y reads; 32768 atomics on 1000
// counters (~33 per address) -> a few us, launch-overhead dominated.
__global__ void scatter_kernel(const int4* __restrict__ y4, int n4) {
    int i = blockIdx.x * blockDim.x + threadIdx.x;
    if (i >= n4) return;
    int4 c = y4[i];
    int base = i * 4;
    int p0 = atomicAdd(&g_count[c.x], 1);
    if (p0 < CAP) g_perm[c.x * CAP + p0] = base + 0;
    int p1 = atomicAdd(&g_count[c.y], 1);
    if (p1 < CAP) g_perm[c.y * CAP + p1] = base + 1;
    int p2 = atomicAdd(&g_count[c.z], 1);
    if (p2 < CAP) g_perm[c.z * CAP + p2] = base + 2;
    int p3 = atomicAdd(&g_count[c.w], 1);
    if (p3 < CAP) g_perm[c.w * CAP + p3] = base + 3;
}

// K2: one CTA per class. Gather ~33 rows (4KB each, fully coalesced),
// reduce in registers, blend with centroid, write output. No atomics on the
// 134MB path. Resets g_count[c] afterwards (self-cleaning for next replay).
__global__ void __launch_bounds__(VEC4, 4)
sum_blend_kernel(const float* __restrict__ embed,
                 const float* __restrict__ centroid,
                 float* __restrict__ out) {
    const int c = blockIdx.x;
    const int t = threadIdx.x;            // 0..255, each thread owns 4 columns

    // Uniform-per-CTA count: one L2/L1 request, broadcast across the warp.
    int n = __ldg(&g_count[c]);
    n = (n < CAP) ? n : CAP;

    __shared__ int s_rows[CAP];
    for (int r = t; r < n; r += VEC4) s_rows[r] = g_perm[c * CAP + r];
    __syncthreads();

    const float4* __restrict__ e4 = (const float4*)embed;

    float ax = 0.f, ay = 0.f, az = 0.f, aw = 0.f;

    int r = 0;
    // 4 independent 16B loads in flight per thread (MLP>=4)
    for (; r + 4 <= n; r += 4) {
        long long i0 = s_rows[r + 0];
        long long i1 = s_rows[r + 1];
        long long i2 = s_rows[r + 2];
        long long i3 = s_rows[r + 3];
        float4 v0 = e4[i0 * VEC4 + t];
        float4 v1 = e4[i1 * VEC4 + t];
        float4 v2 = e4[i2 * VEC4 + t];
        float4 v3 = e4[i3 * VEC4 + t];
        ax += v0.x + v1.x + v2.x + v3.x;
        ay += v0.y + v1.y + v2.y + v3.y;
        az += v0.z + v1.z + v2.z + v3.z;
        aw += v0.w + v1.w + v2.w + v3.w;
    }
    for (; r < n; ++r) {
        long long i0 = s_rows[r];
        float4 v0 = e4[i0 * VEC4 + t];
        ax += v0.x; ay += v0.y; az += v0.z; aw += v0.w;
    }

    // Reset counter for the next graph replay (after everyone consumed n;
    // n was read before, and only this CTA touches class c).
    if (t == 0) g_count[c] = 0;

    // FACTOR * (sum / n) + (1 - FACTOR) * centroid
    const float inv = FACTOR / (float)n;   // n==0 -> NaN, matches ref 0/0
    const float4 ct = ((const float4*)centroid)[c * VEC4 + t];

    float4 o;
    o.x = ax * inv + (1.0f - FACTOR) * ct.x;
    o.y = ay * inv + (1.0f - FACTOR) * ct.y;
    o.z = az * inv + (1.0f - FACTOR) * ct.z;
    o.w = aw * inv + (1.0f - FACTOR) * ct.w;
    ((float4*)out)[c * VEC4 + t] = o;
}

extern "C" void kernel_launch(void* const* d_in, const int* in_sizes, int n_in,
                              void* d_out, int out_size) {
    const float* embed    = (const float*)d_in[0];
    const int*   y        = (const int*)d_in[1];
    const float* centroid = (const float*)d_in[2];
    float*       out      = (float*)d_out;
    const int    batch    = in_sizes[1];   // 32768 (multiple of 4)
    const int    n4       = batch / 4;

    scatter_kernel<<<(n4 + 255) / 256, 256>>>((const int4*)y, n4);
    sum_blend_kernel<<<NUM_CLASSES, VEC4>>>(embed, centroid, out);
}

// round 4
// speedup vs baseline: 1.0471x; 1.0471x over previous
#include <cuda_runtime.h>
#include <cuda_bf16.h>
#include <cstdint>

#define NUM_CLASSES 1000
#define EMBED_DIM   1024
#define ROW_VEC4    (EMBED_DIM / 4)     // 256 float4 per row
#define FACTOR      0.3f
#define CAP         160                 // max rows per class (E[n]=32.8, sigma=5.7)
#define CHUNKS      4                   // column chunks per class
#define BLK         (ROW_VEC4 / CHUNKS) // 64 threads, each owns one float4

// Scratch (__device__ globals: no allocation allowed).
// INVARIANT: g_count and g_done are all-zero at entry of every execution:
// zero-initialized at load; K2's last-arriving chunk CTA per class resets both.
__device__ int g_count[NUM_CLASSES];
__device__ int g_done[NUM_CLASSES];
__device__ int g_perm[NUM_CLASSES * CAP];

// K1: bucket rows by class. int4-vectorized y reads; ~33 atomics/address.
__global__ void scatter_kernel(const int4* __restrict__ y4, int n4) {
    int i = blockIdx.x * blockDim.x + threadIdx.x;
    if (i >= n4) return;
    int4 c = y4[i];
    int base = i * 4;
    int p0 = atomicAdd(&g_count[c.x], 1);
    if (p0 < CAP) g_perm[c.x * CAP + p0] = base + 0;
    int p1 = atomicAdd(&g_count[c.y], 1);
    if (p1 < CAP) g_perm[c.y * CAP + p1] = base + 1;
    int p2 = atomicAdd(&g_count[c.z], 1);
    if (p2 < CAP) g_perm[c.z * CAP + p2] = base + 2;
    int p3 = atomicAdd(&g_count[c.w], 1);
    if (p3 < CAP) g_perm[c.w * CAP + p3] = base + 3;
}

// K2: grid = NUM_CLASSES * CHUNKS. CTA b handles class b/CHUNKS, column chunk
// b%CHUNKS (64 float4 columns). Gather ~33 partial rows (1KB each, coalesced),
// reduce in registers, blend, write. No atomics on the 134MB path.
__global__ void __launch_bounds__(BLK)
sum_blend_kernel(const float* __restrict__ embed,
                 const float* __restrict__ centroid,
                 float* __restrict__ out) {
    const int c     = blockIdx.x >> 2;        // class
    const int chunk = blockIdx.x & 3;         // column chunk
    const int t     = threadIdx.x;            // 0..63
    const int col   = chunk * BLK + t;        // float4 column within row

    int n = __ldg(&g_count[c]);
    n = (n < CAP) ? n : CAP;

    __shared__ int s_rows[CAP];
    for (int r = t; r < n; r += BLK) s_rows[r] = g_perm[c * CAP + r];
    __syncthreads();

    const float4* __restrict__ e4 = (const float4*)embed;

    float ax = 0.f, ay = 0.f, az = 0.f, aw = 0.f;

    int r = 0;
    for (; r + 4 <= n; r += 4) {               // 4 independent LDG.128 in flight
        long long i0 = s_rows[r + 0];
        long long i1 = s_rows[r + 1];
        long long i2 = s_rows[r + 2];
        long long i3 = s_rows[r + 3];
        float4 v0 = e4[i0 * ROW_VEC4 + col];
        float4 v1 = e4[i1 * ROW_VEC4 + col];
        float4 v2 = e4[i2 * ROW_VEC4 + col];
        float4 v3 = e4[i3 * ROW_VEC4 + col];
        ax += v0.x + v1.x + v2.x + v3.x;
        ay += v0.y + v1.y + v2.y + v3.y;
        az += v0.z + v1.z + v2.z + v3.z;
        aw += v0.w + v1.w + v2.w + v3.w;
    }
    for (; r < n; ++r) {
        long long i0 = s_rows[r];
        float4 v0 = e4[i0 * ROW_VEC4 + col];
        ax += v0.x; ay += v0.y; az += v0.z; aw += v0.w;
    }

    // blend + store
    const float inv = FACTOR / (float)n;       // n==0 -> NaN, matches ref 0/0
    const float4 ct = ((const float4*)centroid)[c * ROW_VEC4 + col];
    float4 o;
    o.x = ax * inv + (1.0f - FACTOR) * ct.x;
    o.y = ay * inv + (1.0f - FACTOR) * ct.y;
    o.z = az * inv + (1.0f - FACTOR) * ct.z;
    o.w = aw * inv + (1.0f - FACTOR) * ct.w;
    ((float4*)out)[c * ROW_VEC4 + col] = o;

    // Self-cleaning reset: last-arriving chunk CTA for this class zeroes the
    // counters. Every CTA read g_count BEFORE arriving (fence orders it).
    __syncthreads();
    if (t == 0) {
        __threadfence();
        int old = atomicAdd(&g_done[c], 1);
        if (old == CHUNKS - 1) {
            g_count[c] = 0;
            g_done[c]  = 0;
        }
    }
}

extern "C" void kernel_launch(void* const* d_in, const int* in_sizes, int n_in,
                              void* d_out, int out_size) {
    const float* embed    = (const float*)d_in[0];
    const int*   y        = (const int*)d_in[1];
    const float* centroid = (const float*)d_in[2];
    float*       out      = (float*)d_out;
    const int    batch    = in_sizes[1];   // 32768 (multiple of 4)
    const int    n4       = batch / 4;

    scatter_kernel<<<(n4 + 255) / 256, 256>>>((const int4*)y, n4);
    sum_blend_kernel<<<NUM_CLASSES * CHUNKS, BLK>>>(embed, centroid, out);
}